// round 11
// baseline (speedup 1.0000x reference)
#include <cuda_runtime.h>
#include <stdint.h>

#define NBS 8192        // B*S
#define DD  512
#define SS  2048
#define WLD 4100
#define NBEAM 10
#define PLANE ((size_t)NBEAM * NBS * DD)

// ---------------- static device scratch (allocation-free) -------------------
static __device__ float g_c[(size_t)SS * SS];
static __device__ float g_ct[(size_t)NBS * DD];
static __device__ float g_h[(size_t)NBS * DD];
static __device__ float g_states0[(size_t)NBS * DD];
static __device__ float g_goal[(size_t)NBS * DD];
static __device__ float g_gp[(size_t)NBS * DD];
static __device__ float g_Sb[2][PLANE];          // fallback only
static __device__ float g_Yb[2][PLANE];          // plane0/parity0 = Y0; rest fallback
static __device__ int   g_root[2][NBEAM * NBS];
static __device__ float g_s1[DD], g_t1[DD], g_A1[8 * DD];
static __device__ float g_W2t[8 * DD];
static __device__ double g_sm0[NBS], g_su0[NBS], g_sr0[NBS];
static __device__ double g_sq0[(size_t)NBS * 8];
static __device__ double g_sumA[8], g_nA[8], g_lA[8], g_AB[64], g_sumL, g_nL;
static __device__ int   g_flag;

// ---------------- helpers ----------------------------------------------------
__device__ __forceinline__ float block_sum256(float v, float* red) {
#pragma unroll
    for (int o = 16; o; o >>= 1) v += __shfl_xor_sync(0xffffffffu, v, o);
    if ((threadIdx.x & 31) == 0) red[threadIdx.x >> 5] = v;
    __syncthreads();
    float s = red[0] + red[1] + red[2] + red[3] + red[4] + red[5] + red[6] + red[7];
    __syncthreads();
    return s;
}

__global__ void flag_k(const float* __restrict__ g) {
    __shared__ int ok;
    if (threadIdx.x == 0) ok = 1;
    __syncthreads();
    if (g[threadIdx.x] != 1.0f) atomicExch(&ok, 0);
    __syncthreads();
    if (threadIdx.x == 0) g_flag = ok;
}

// s1 = colsum(W1a); t1 = ln_b @ W1a; A1[a] = action[a] @ W1a
__global__ __launch_bounds__(128) void precomp_k(
    const float* __restrict__ W1a, const float* __restrict__ action,
    const float* __restrict__ lnb)
{
    int n = blockIdx.x, t = threadIdx.x;
    float v[10];
#pragma unroll
    for (int i = 0; i < 10; i++) v[i] = 0.f;
    for (int d = t; d < DD; d += 128) {
        float w = W1a[(size_t)d * DD + n];
        v[0] += w;
        v[1] += lnb[d] * w;
#pragma unroll
        for (int a = 0; a < 8; a++) v[2 + a] += action[a * DD + d] * w;
    }
    __shared__ float red[10][4];
    int wd = t >> 5, ln = t & 31;
#pragma unroll
    for (int i = 0; i < 10; i++) {
        float x = v[i];
#pragma unroll
        for (int o = 16; o; o >>= 1) x += __shfl_xor_sync(0xffffffffu, x, o);
        if (ln == 0) red[i][wd] = x;
    }
    __syncthreads();
    if (t < 10) {
        float s = red[t][0] + red[t][1] + red[t][2] + red[t][3];
        if (t == 0)      g_s1[n] = s;
        else if (t == 1) g_t1[n] = s;
        else             g_A1[(t - 2) * DD + n] = s;
    }
}

// double-precision action/lnb constants + W2 transpose
__global__ __launch_bounds__(256) void const_k(
    const float* __restrict__ action, const float* __restrict__ lnb,
    const float* __restrict__ W2)
{
    int a = blockIdx.x, t = threadIdx.x;
    double v[13];
#pragma unroll
    for (int i = 0; i < 13; i++) v[i] = 0.0;
    for (int d = t; d < DD; d += 256) {
        double ad = (double)action[a * DD + d];
        double ld = (double)lnb[d];
        v[0] += ad; v[1] += ad * ad; v[2] += ad * ld;
#pragma unroll
        for (int b = 0; b < 8; b++) v[3 + b] += ad * (double)action[b * DD + d];
        v[11] += ld; v[12] += ld * ld;
    }
    __shared__ double dred[13][8];
    int wp = t >> 5, ln = t & 31;
#pragma unroll
    for (int i = 0; i < 13; i++) {
        double x = v[i];
#pragma unroll
        for (int o = 16; o; o >>= 1) x += __shfl_xor_sync(0xffffffffu, x, o);
        if (ln == 0) dred[i][wp] = x;
    }
    __syncthreads();
    if (t < 13) {
        double s = 0.0;
#pragma unroll
        for (int w = 0; w < 8; w++) s += dred[t][w];
        if (t == 0)      g_sumA[a] = s;
        else if (t == 1) g_nA[a] = s;
        else if (t == 2) g_lA[a] = s;
        else if (t < 11) g_AB[a * 8 + (t - 3)] = s;
        else if (a == 0 && t == 11) g_sumL = s;
        else if (a == 0 && t == 12) g_nL = s;
    }
    if (a == 0)
        for (int idx = t; idx < 4096; idx += 256)
            g_W2t[(idx & 7) * DD + (idx >> 3)] = W2[idx];
}

// initial scalar stats of states0
__global__ __launch_bounds__(128) void initstats_k(
    const float* __restrict__ lnb, const float* __restrict__ action)
{
    int bs = blockIdx.x, t = threadIdx.x;
    float4 s = ((const float4*)(g_states0 + (size_t)bs * DD))[t];
    double a0 = s.x, a1 = s.y, a2 = s.z, a3 = s.w;
    double v[11];
    v[0] = a0 + a1 + a2 + a3;
    v[1] = a0 * a0 + a1 * a1 + a2 * a2 + a3 * a3;
    float4 l = ((const float4*)lnb)[t];
    v[2] = a0 * l.x + a1 * l.y + a2 * l.z + a3 * l.w;
#pragma unroll
    for (int b = 0; b < 8; b++) {
        float4 w = ((const float4*)(action + b * DD))[t];
        v[3 + b] = a0 * w.x + a1 * w.y + a2 * w.z + a3 * w.w;
    }
    __shared__ double dred[11][4];
    int wp = t >> 5, ln = t & 31;
#pragma unroll
    for (int i = 0; i < 11; i++) {
        double x = v[i];
#pragma unroll
        for (int o = 16; o; o >>= 1) x += __shfl_xor_sync(0xffffffffu, x, o);
        if (ln == 0) dred[i][wp] = x;
    }
    __syncthreads();
    if (t < 11) {
        double s2 = dred[t][0] + dred[t][1] + dred[t][2] + dred[t][3];
        if (t == 0)      g_sm0[bs] = s2;
        else if (t == 1) g_su0[bs] = s2;
        else if (t == 2) g_sr0[bs] = s2;
        else             g_sq0[(size_t)bs * 8 + (t - 3)] = s2;
    }
}

// ---------------- double-buffered 128x128 M x 512 x 512 SGEMM ----------------
__global__ __launch_bounds__(256) void gemm512_k(
    const float* __restrict__ A, const float* __restrict__ W,
    const float* __restrict__ bias, float* __restrict__ C, int relu)
{
    __shared__ float As[2][16][132];
    __shared__ float Ws[2][16][132];
    int n0 = blockIdx.x * 128, m0 = blockIdx.y * 128;
    int tid = threadIdx.x, tm = tid >> 4, tn = tid & 15;
    float acc[8][8];
#pragma unroll
    for (int i = 0; i < 8; i++)
#pragma unroll
        for (int j = 0; j < 8; j++) acc[i][j] = 0.f;

    int r0 = tid >> 2, c0 = (tid & 3) << 2;
    int r1 = (tid + 256) >> 2, c1 = ((tid + 256) & 3) << 2;
    int rw0 = tid >> 5, cw0 = (tid & 31) << 2;
    int rw1 = (tid + 256) >> 5, cw1 = ((tid + 256) & 31) << 2;

    float4 pa0, pa1, pw0, pw1;
    pa0 = *(const float4*)(A + (size_t)(m0 + r0) * DD + c0);
    pa1 = *(const float4*)(A + (size_t)(m0 + r1) * DD + c1);
    pw0 = *(const float4*)(W + (size_t)rw0 * DD + n0 + cw0);
    pw1 = *(const float4*)(W + (size_t)rw1 * DD + n0 + cw1);
    As[0][c0][r0] = pa0.x; As[0][c0 + 1][r0] = pa0.y; As[0][c0 + 2][r0] = pa0.z; As[0][c0 + 3][r0] = pa0.w;
    As[0][c1][r1] = pa1.x; As[0][c1 + 1][r1] = pa1.y; As[0][c1 + 2][r1] = pa1.z; As[0][c1 + 3][r1] = pa1.w;
    *(float4*)&Ws[0][rw0][cw0] = pw0;
    *(float4*)&Ws[0][rw1][cw1] = pw1;
    __syncthreads();

    int buf = 0;
    for (int k0 = 0; k0 < DD; k0 += 16) {
        int nk = k0 + 16;
        if (nk < DD) {
            pa0 = *(const float4*)(A + (size_t)(m0 + r0) * DD + nk + c0);
            pa1 = *(const float4*)(A + (size_t)(m0 + r1) * DD + nk + c1);
            pw0 = *(const float4*)(W + (size_t)(nk + rw0) * DD + n0 + cw0);
            pw1 = *(const float4*)(W + (size_t)(nk + rw1) * DD + n0 + cw1);
        }
#pragma unroll
        for (int kk = 0; kk < 16; kk++) {
            float a[8], b[8];
            *(float4*)a       = *(const float4*)&As[buf][kk][tm * 8];
            *(float4*)(a + 4) = *(const float4*)&As[buf][kk][tm * 8 + 4];
            *(float4*)b       = *(const float4*)&Ws[buf][kk][tn * 8];
            *(float4*)(b + 4) = *(const float4*)&Ws[buf][kk][tn * 8 + 4];
#pragma unroll
            for (int i = 0; i < 8; i++)
#pragma unroll
                for (int j = 0; j < 8; j++) acc[i][j] += a[i] * b[j];
        }
        if (nk < DD) {
            int nb = buf ^ 1;
            As[nb][c0][r0] = pa0.x; As[nb][c0 + 1][r0] = pa0.y; As[nb][c0 + 2][r0] = pa0.z; As[nb][c0 + 3][r0] = pa0.w;
            As[nb][c1][r1] = pa1.x; As[nb][c1 + 1][r1] = pa1.y; As[nb][c1 + 2][r1] = pa1.z; As[nb][c1 + 3][r1] = pa1.w;
            *(float4*)&Ws[nb][rw0][cw0] = pw0;
            *(float4*)&Ws[nb][rw1][cw1] = pw1;
            __syncthreads();
            buf = nb;
        }
    }
#pragma unroll
    for (int i = 0; i < 8; i++) {
        int row = m0 + tm * 8 + i;
#pragma unroll
        for (int j = 0; j < 8; j++) {
            int col = n0 + tn * 8 + j;
            float v = acc[i][j];
            if (bias) v += bias[col];
            if (relu) v = fmaxf(v, 0.f);
            C[(size_t)row * DD + col] = v;
        }
    }
}

// ---------------- double-buffered 128x128 triangular GEMM --------------------
__global__ __launch_bounds__(256) void gemmtri_k(
    const float* __restrict__ A, const float* __restrict__ Wt)
{
    __shared__ float As[2][16][132];
    __shared__ float Ws[2][16][132];
    int n0 = blockIdx.x * 128, m0 = blockIdx.y * 128;
    int tid = threadIdx.x, tm = tid >> 4, tn = tid & 15;
    float acc[8][8];
#pragma unroll
    for (int i = 0; i < 8; i++)
#pragma unroll
        for (int j = 0; j < 8; j++) acc[i][j] = 0.f;

    int r0 = tid >> 2, c0 = (tid & 3) << 2;
    int r1 = (tid + 256) >> 2, c1 = ((tid + 256) & 3) << 2;
    int rw0 = tid >> 5, cw0 = (tid & 31) << 2;
    int rw1 = (tid + 256) >> 5, cw1 = ((tid + 256) & 31) << 2;

    auto loadw = [&](int k0, int r, int c) -> float4 {
        int tt = k0 + r;
        if (k0 - n0 < 128) {
            int s = n0 + c;
            float4 w;
            w.x = (tt >= s    ) ? Wt[(size_t)tt * WLD + s    ] : 0.f;
            w.y = (tt >= s + 1) ? Wt[(size_t)tt * WLD + s + 1] : 0.f;
            w.z = (tt >= s + 2) ? Wt[(size_t)tt * WLD + s + 2] : 0.f;
            w.w = (tt >= s + 3) ? Wt[(size_t)tt * WLD + s + 3] : 0.f;
            return w;
        }
        return *(const float4*)(Wt + (size_t)tt * WLD + n0 + c);
    };

    float4 pa0, pa1, pw0, pw1;
    pa0 = *(const float4*)(A + (size_t)(m0 + r0) * SS + n0 + c0);
    pa1 = *(const float4*)(A + (size_t)(m0 + r1) * SS + n0 + c1);
    pw0 = loadw(n0, rw0, cw0);
    pw1 = loadw(n0, rw1, cw1);
    As[0][c0][r0] = pa0.x; As[0][c0 + 1][r0] = pa0.y; As[0][c0 + 2][r0] = pa0.z; As[0][c0 + 3][r0] = pa0.w;
    As[0][c1][r1] = pa1.x; As[0][c1 + 1][r1] = pa1.y; As[0][c1 + 2][r1] = pa1.z; As[0][c1 + 3][r1] = pa1.w;
    *(float4*)&Ws[0][rw0][cw0] = pw0;
    *(float4*)&Ws[0][rw1][cw1] = pw1;
    __syncthreads();

    int buf = 0;
    for (int k0 = n0; k0 < SS; k0 += 16) {
        int nk = k0 + 16;
        if (nk < SS) {
            pa0 = *(const float4*)(A + (size_t)(m0 + r0) * SS + nk + c0);
            pa1 = *(const float4*)(A + (size_t)(m0 + r1) * SS + nk + c1);
            pw0 = loadw(nk, rw0, cw0);
            pw1 = loadw(nk, rw1, cw1);
        }
#pragma unroll
        for (int kk = 0; kk < 16; kk++) {
            float a[8], b[8];
            *(float4*)a       = *(const float4*)&As[buf][kk][tm * 8];
            *(float4*)(a + 4) = *(const float4*)&As[buf][kk][tm * 8 + 4];
            *(float4*)b       = *(const float4*)&Ws[buf][kk][tn * 8];
            *(float4*)(b + 4) = *(const float4*)&Ws[buf][kk][tn * 8 + 4];
#pragma unroll
            for (int i = 0; i < 8; i++)
#pragma unroll
                for (int j = 0; j < 8; j++) acc[i][j] += a[i] * b[j];
        }
        if (nk < SS) {
            int nb = buf ^ 1;
            As[nb][c0][r0] = pa0.x; As[nb][c0 + 1][r0] = pa0.y; As[nb][c0 + 2][r0] = pa0.z; As[nb][c0 + 3][r0] = pa0.w;
            As[nb][c1][r1] = pa1.x; As[nb][c1 + 1][r1] = pa1.y; As[nb][c1 + 2][r1] = pa1.z; As[nb][c1 + 3][r1] = pa1.w;
            *(float4*)&Ws[nb][rw0][cw0] = pw0;
            *(float4*)&Ws[nb][rw1][cw1] = pw1;
            __syncthreads();
            buf = nb;
        }
    }
#pragma unroll
    for (int i = 0; i < 8; i++) {
        int row = m0 + tm * 8 + i;
#pragma unroll
        for (int j = 0; j < 8; j++)
            g_c[(size_t)row * SS + n0 + tn * 8 + j] = fmaxf(acc[i][j], 0.f);
    }
}

// ---------------- transposes -------------------------------------------------
__global__ void transpose_c_k() {
    __shared__ float tile[32][33];
    int b = blockIdx.z, s0 = blockIdx.x * 32, d0 = blockIdx.y * 32;
    int tx = threadIdx.x, ty = threadIdx.y;
#pragma unroll
    for (int i = 0; i < 32; i += 8)
        tile[ty + i][tx] = g_c[(size_t)(b * DD + d0 + ty + i) * SS + s0 + tx];
    __syncthreads();
#pragma unroll
    for (int i = 0; i < 32; i += 8)
        g_ct[(size_t)(b * SS + s0 + ty + i) * DD + d0 + tx] = tile[tx][ty + i];
}
__global__ void transpose_out_k(float* __restrict__ out) {
    __shared__ float tile[32][33];
    int b = blockIdx.z, d0 = blockIdx.x * 32, s0 = blockIdx.y * 32;
    int tx = threadIdx.x, ty = threadIdx.y;
#pragma unroll
    for (int i = 0; i < 32; i += 8)
        tile[ty + i][tx] = g_h[(size_t)(b * SS + s0 + ty + i) * DD + d0 + tx];
    __syncthreads();
#pragma unroll
    for (int i = 0; i < 32; i += 8)
        out[(size_t)(b * DD + d0 + ty + i) * SS + s0 + tx] = tile[tx][ty + i];
}

__global__ void copy_k() {   // states0 -> S plane0 (fallback path seed)
    size_t i = (size_t)blockIdx.x * 256 + threadIdx.x;
    ((float4*)g_Sb[0])[i] = ((const float4*)g_states0)[i];
}

// ============ fused persistent beam kernel: one block per (b,s) ==============
// dynamic smem layout (doubles first for alignment)
#define BK_SMEM 82304
__global__ __launch_bounds__(256) void beam_k(
    const float* __restrict__ action, const float* __restrict__ lng,
    const float* __restrict__ lnb, const float* __restrict__ W1a,
    const float* __restrict__ b2)
{
    extern __shared__ double dyn[];
    double* dSM = dyn;            // [2][10]
    double* dSU = dSM + 20;
    double* dSR = dSU + 20;
    double* dSQ = dSR + 20;       // [2][10][8]
    float* YB   = (float*)(dyn + 220);   // [2][10][512]
    float* sW2t = YB + 10240;     // [8][512]
    float* sA1  = sW2t + 4096;    // [8][512]
    float* ss1  = sA1 + 4096;     // 512
    float* st1  = ss1 + 512;      // 512
    float* sgp  = st1 + 512;      // 512
    float* sb2  = sgp + 512;      // 8
    float* slog = sb2 + 8;        // 80
    float* sprob= slog + 80;      // [2][10]
    float* smu  = sprob + 20;     // 10
    float* siv  = smu + 10;       // 10
    int* sselp  = (int*)(siv + 10);   // 10
    int* ssela  = sselp + 10;         // 10
    int* sroot  = ssela + 10;         // [2][10]

    int bs = blockIdx.x;
    int tid = threadIdx.x;
    int lane = tid & 31, wp = tid >> 5;
    int flag = g_flag;

    for (int i = tid; i < 4096; i += 256) { sW2t[i] = g_W2t[i]; sA1[i] = g_A1[i]; }
    for (int i = tid; i < 512; i += 256) {
        ss1[i] = g_s1[i]; st1[i] = g_t1[i];
        sgp[i] = g_gp[(size_t)bs * DD + i];
    }
    if (tid < 8) sb2[tid] = b2[tid];
    if (flag) {
        for (int i = tid; i < 512; i += 256)
            YB[i] = g_Yb[0][(size_t)bs * DD + i];
        if (tid == 0) { dSM[0] = g_sm0[bs]; dSU[0] = g_su0[bs]; dSR[0] = g_sr0[bs]; }
        if (tid < 8) dSQ[tid] = g_sq0[(size_t)bs * 8 + tid];
    }
    if (tid == 0) sprob[0] = 1.0f;
    __syncthreads();

    const int bn[7] = {1, 8, 10, 10, 10, 10, 10};
    const int bx[7] = {8, 10, 10, 10, 10, 10, 10};
    int pc = 0;

    if (flag) {
        // ------------------ fast path: all in smem ------------------
        for (int t = 0; t < 7; t++) {
            int beam_now = bn[t], beam_next = bx[t];
            float* Yc = YB + pc * 5120;
            float* Yn = YB + (pc ^ 1) * 5120;
            // logits: warp per beam
            for (int kb = wp; kb < beam_now; kb += 8) {
                const float* y = Yc + kb * 512;
                float acc[8] = {0, 0, 0, 0, 0, 0, 0, 0};
#pragma unroll
                for (int j = 0; j < 16; j++) {
                    int n = lane + j * 32;
                    float h = fmaxf(y[n] + sgp[n], 0.f);
#pragma unroll
                    for (int a = 0; a < 8; a++) acc[a] += h * sW2t[a * 512 + n];
                }
#pragma unroll
                for (int a = 0; a < 8; a++) {
                    float v = acc[a];
#pragma unroll
                    for (int o = 16; o; o >>= 1) v += __shfl_xor_sync(0xffffffffu, v, o);
                    if (lane == 0) slog[kb * 8 + a] = v + sb2[a];
                }
            }
            __syncthreads();
            // select on warp 0
            if (tid < 32) {
                float c[8];
                if (lane < beam_now) {
                    float l[8], m = -1e30f;
#pragma unroll
                    for (int a = 0; a < 8; a++) { l[a] = slog[lane * 8 + a]; m = fmaxf(m, l[a]); }
                    float s = 0.f;
#pragma unroll
                    for (int a = 0; a < 8; a++) { l[a] = expf(l[a] - m); s += l[a]; }
                    float pk = sprob[pc * 10 + lane];
#pragma unroll
                    for (int a = 0; a < 8; a++) c[a] = pk * (l[a] / s);
                } else {
#pragma unroll
                    for (int a = 0; a < 8; a++) c[a] = -2.f;
                }
                float myv = 0.f; int myi = 0;
                for (int k = 0; k < beam_next; k++) {
                    float v = -3.f; int id = 0x7fffffff;
#pragma unroll
                    for (int a = 0; a < 8; a++)
                        if (c[a] > v) { v = c[a]; id = lane * 8 + a; }
#pragma unroll
                    for (int o = 16; o; o >>= 1) {
                        float ov = __shfl_xor_sync(0xffffffffu, v, o);
                        int   oi = __shfl_xor_sync(0xffffffffu, id, o);
                        if (ov > v || (ov == v && oi < id)) { v = ov; id = oi; }
                    }
                    if ((id >> 3) == lane) c[id & 7] = -1.f;
                    if (lane == k) { myv = v; myi = id; }
                }
                if (lane < beam_next) {
                    int parent = myi >> 3, act = myi & 7;
                    sprob[(pc ^ 1) * 10 + lane] = myv;
                    sselp[lane] = parent; ssela[lane] = act;
                    sroot[(pc ^ 1) * 10 + lane] = (t == 0) ? act : sroot[pc * 10 + parent];
                    double m_ = dSM[pc * 10 + parent], u = dSU[pc * 10 + parent], r = dSR[pc * 10 + parent];
                    const double* qp = &dSQ[pc * 80 + parent * 8];
                    double sum_h = m_ + g_sumA[act];
                    double mu = sum_h * (1.0 / 512.0);
                    double hh = u + 2.0 * qp[act] + g_nA[act];
                    double var = hh * (1.0 / 512.0) - mu * mu;
                    double inv = rsqrt(var + 1e-5);
                    smu[lane] = (float)mu; siv[lane] = (float)inv;
                    double hml = r + g_lA[act] - mu * g_sumL;
                    dSM[(pc ^ 1) * 10 + lane] = inv * (sum_h - 512.0 * mu) + g_sumL;
                    dSU[(pc ^ 1) * 10 + lane] = inv * inv * (hh - 512.0 * mu * mu) + 2.0 * inv * hml + g_nL;
                    dSR[(pc ^ 1) * 10 + lane] = inv * hml + g_nL;
                    double* qn = &dSQ[(pc ^ 1) * 80 + lane * 8];
#pragma unroll
                    for (int b = 0; b < 8; b++)
                        qn[b] = inv * (qp[b] + g_AB[act * 8 + b] - mu * g_sumA[b]) + g_lA[b];
                }
            }
            __syncthreads();
            // Y recursion in smem
            if (t < 6) {
                const float4* Yc4 = (const float4*)Yc;
                float4* Yn4 = (float4*)Yn;
                const float4* A14 = (const float4*)sA1;
                const float4* s14 = (const float4*)ss1;
                const float4* t14 = (const float4*)st1;
                int tot = beam_next * 128;
                for (int ii = tid; ii < tot; ii += 256) {
                    int k = ii >> 7, d = ii & 127;
                    int p = sselp[k], a = ssela[k];
                    float mu = smu[k], inv = siv[k];
                    float4 yp = Yc4[p * 128 + d];
                    float4 aa = A14[a * 128 + d];
                    float4 s4 = s14[d], t4 = t14[d];
                    float4 yo;
                    yo.x = fmaf(inv, yp.x + aa.x - mu * s4.x, t4.x);
                    yo.y = fmaf(inv, yp.y + aa.y - mu * s4.y, t4.y);
                    yo.z = fmaf(inv, yp.z + aa.z - mu * s4.z, t4.z);
                    yo.w = fmaf(inv, yp.w + aa.w - mu * s4.w, t4.w);
                    Yn4[k * 128 + d] = yo;
                }
                __syncthreads();
            }
            pc ^= 1;
        }
    } else {
        // ------------------ exact fallback: gmem planes ------------------
        for (int t = 0; t < 7; t++) {
            int beam_now = bn[t], beam_next = bx[t];
            for (int kb = wp; kb < beam_now; kb += 8) {
                const float* y = g_Yb[pc] + ((size_t)kb * NBS + bs) * DD;
                float acc[8] = {0, 0, 0, 0, 0, 0, 0, 0};
#pragma unroll
                for (int j = 0; j < 16; j++) {
                    int n = lane + j * 32;
                    float h = fmaxf(y[n] + sgp[n], 0.f);
#pragma unroll
                    for (int a = 0; a < 8; a++) acc[a] += h * sW2t[a * 512 + n];
                }
#pragma unroll
                for (int a = 0; a < 8; a++) {
                    float v = acc[a];
#pragma unroll
                    for (int o = 16; o; o >>= 1) v += __shfl_xor_sync(0xffffffffu, v, o);
                    if (lane == 0) slog[kb * 8 + a] = v + sb2[a];
                }
            }
            __syncthreads();
            if (tid < 32) {
                float c[8];
                if (lane < beam_now) {
                    float l[8], m = -1e30f;
#pragma unroll
                    for (int a = 0; a < 8; a++) { l[a] = slog[lane * 8 + a]; m = fmaxf(m, l[a]); }
                    float s = 0.f;
#pragma unroll
                    for (int a = 0; a < 8; a++) { l[a] = expf(l[a] - m); s += l[a]; }
                    float pk = sprob[pc * 10 + lane];
#pragma unroll
                    for (int a = 0; a < 8; a++) c[a] = pk * (l[a] / s);
                } else {
#pragma unroll
                    for (int a = 0; a < 8; a++) c[a] = -2.f;
                }
                float myv = 0.f; int myi = 0;
                for (int k = 0; k < beam_next; k++) {
                    float v = -3.f; int id = 0x7fffffff;
#pragma unroll
                    for (int a = 0; a < 8; a++)
                        if (c[a] > v) { v = c[a]; id = lane * 8 + a; }
#pragma unroll
                    for (int o = 16; o; o >>= 1) {
                        float ov = __shfl_xor_sync(0xffffffffu, v, o);
                        int   oi = __shfl_xor_sync(0xffffffffu, id, o);
                        if (ov > v || (ov == v && oi < id)) { v = ov; id = oi; }
                    }
                    if ((id >> 3) == lane) c[id & 7] = -1.f;
                    if (lane == k) { myv = v; myi = id; }
                }
                if (lane < beam_next) {
                    sprob[(pc ^ 1) * 10 + lane] = myv;
                    sselp[lane] = myi >> 3; ssela[lane] = myi & 7;
                    sroot[(pc ^ 1) * 10 + lane] = (t == 0) ? (myi & 7) : sroot[pc * 10 + (myi >> 3)];
                }
            }
            __syncthreads();
            if (t < 6) {
                float* sn = YB;          // scratch 512
                float* red = YB + 512;   // 8
                for (int k = 0; k < beam_next; k++) {
                    int p = sselp[k], a = ssela[k];
                    const float* Sp = g_Sb[pc] + ((size_t)p * NBS + bs) * DD;
                    float* Sn = g_Sb[pc ^ 1] + ((size_t)k * NBS + bs) * DD;
                    float h0 = Sp[tid]       + action[a * DD + tid];
                    float h1 = Sp[tid + 256] + action[a * DD + tid + 256];
                    float mu = block_sum256(h0 + h1, red) * (1.f / 512.f);
                    float d0 = h0 - mu, d1 = h1 - mu;
                    float var = block_sum256(d0 * d0 + d1 * d1, red) * (1.f / 512.f);
                    float inv = rsqrtf(var + 1e-5f);
                    float v0 = d0 * inv * lng[tid]       + lnb[tid];
                    float v1 = d1 * inv * lng[tid + 256] + lnb[tid + 256];
                    sn[tid] = v0; sn[tid + 256] = v1;
                    Sn[tid] = v0; Sn[tid + 256] = v1;
                    __syncthreads();
                    float* Yn = g_Yb[pc ^ 1] + ((size_t)k * NBS + bs) * DD;
                    for (int n = tid; n < 512; n += 256) {
                        float ac = 0.f;
                        for (int d = 0; d < 512; d++) ac += sn[d] * W1a[(size_t)d * DD + n];
                        Yn[n] = ac;
                    }
                    __syncthreads();
                }
            }
            pc ^= 1;
        }
    }
    if (tid == 0) g_root[1][bs] = sroot[pc * 10 + 0];   // pc == 1 after 7 turns
}

// ---------------- final: LN(states0 + action[root0]) -------------------------
__global__ __launch_bounds__(256) void final_k(
    int par, const float* __restrict__ action, const float* __restrict__ lng,
    const float* __restrict__ lnb)
{
    __shared__ float red[8];
    int bs = blockIdx.x, t = threadIdx.x;
    int r = g_root[par][bs];
    float h0 = g_states0[(size_t)bs * DD + t]       + action[r * DD + t];
    float h1 = g_states0[(size_t)bs * DD + t + 256] + action[r * DD + t + 256];
    float mu = block_sum256(h0 + h1, red) * (1.f / 512.f);
    float d0 = h0 - mu, d1 = h1 - mu;
    float var = block_sum256(d0 * d0 + d1 * d1, red) * (1.f / 512.f);
    float inv = rsqrtf(var + 1e-5f);
    g_h[(size_t)bs * DD + t]       = d0 * inv * lng[t]       + lnb[t];
    g_h[(size_t)bs * DD + t + 256] = d1 * inv * lng[t + 256] + lnb[t + 256];
}

// ---------------- launch ------------------------------------------------------
extern "C" void kernel_launch(void* const* d_in, const int* in_sizes, int n_in,
                              void* d_out, int out_size)
{
    const float* x      = (const float*)d_in[0];
    const float* weight = (const float*)d_in[1];
    const float* c2s_w1 = (const float*)d_in[2];
    const float* c2s_b1 = (const float*)d_in[3];
    const float* c2s_w2 = (const float*)d_in[4];
    const float* c2s_b2 = (const float*)d_in[5];
    const float* eg_w1  = (const float*)d_in[6];
    const float* eg_b1  = (const float*)d_in[7];
    const float* eg_w2  = (const float*)d_in[8];
    const float* eg_b2  = (const float*)d_in[9];
    const float* gna_w1 = (const float*)d_in[10];
    const float* gna_b1 = (const float*)d_in[11];
    const float* gna_w2 = (const float*)d_in[12];
    const float* gna_b2 = (const float*)d_in[13];
    const float* action = (const float*)d_in[14];
    const float* ln_g   = (const float*)d_in[15];
    const float* ln_b   = (const float*)d_in[16];

    float *p_ct, *p_h, *p_s0, *p_goal, *p_gp, *p_Y;
    cudaGetSymbolAddress((void**)&p_ct,   g_ct);
    cudaGetSymbolAddress((void**)&p_h,    g_h);
    cudaGetSymbolAddress((void**)&p_s0,   g_states0);
    cudaGetSymbolAddress((void**)&p_goal, g_goal);
    cudaGetSymbolAddress((void**)&p_gp,   g_gp);
    cudaGetSymbolAddress((void**)&p_Y,    g_Yb);
    const float* W1a = gna_w1;
    const float* W1b = gna_w1 + DD * DD;

    cudaFuncSetAttribute(beam_k, cudaFuncAttributeMaxDynamicSharedMemorySize, BK_SMEM);

    flag_k<<<1, 512>>>(ln_g);
    precomp_k<<<512, 128>>>(W1a, action, ln_b);
    const_k<<<8, 256>>>(action, ln_b, gna_w2);
    gemmtri_k<<<dim3(16, 16), 256>>>(x, weight);
    transpose_c_k<<<dim3(64, 16, 4), dim3(32, 8)>>>();
    gemm512_k<<<dim3(4, 64), 256>>>(p_ct,   c2s_w1, c2s_b1, p_h,    1);
    gemm512_k<<<dim3(4, 64), 256>>>(p_h,    c2s_w2, c2s_b2, p_s0,   0);
    gemm512_k<<<dim3(4, 64), 256>>>(p_ct,   eg_w1,  eg_b1,  p_h,    1);
    gemm512_k<<<dim3(4, 64), 256>>>(p_h,    eg_w2,  eg_b2,  p_goal, 0);
    gemm512_k<<<dim3(4, 64), 256>>>(p_goal, W1b,    gna_b1, p_gp,   0);
    gemm512_k<<<dim3(4, 64), 256>>>(p_s0,   W1a,    nullptr, p_Y,   0);
    copy_k<<<4096, 256>>>();
    initstats_k<<<8192, 128>>>(ln_b, action);
    beam_k<<<8192, 256, BK_SMEM>>>(action, ln_g, ln_b, W1a, gna_b2);
    final_k<<<8192, 256>>>(1, action, ln_g, ln_b);
    transpose_out_k<<<dim3(16, 64, 4), dim3(32, 8)>>>((float*)d_out);
}

// round 12
// speedup vs baseline: 1.7048x; 1.7048x over previous
#include <cuda_runtime.h>
#include <stdint.h>

#define NBS 8192        // B*S
#define DD  512
#define SS  2048
#define WLD 4100
#define NBEAM 10
#define PLANE ((size_t)NBEAM * NBS * DD)

// ---------------- static device scratch (allocation-free) -------------------
static __device__ float g_c[(size_t)SS * SS];
static __device__ float g_ct[(size_t)NBS * DD];
static __device__ float g_h[(size_t)NBS * DD];
static __device__ float g_h2[(size_t)NBS * DD];
static __device__ float g_states0[(size_t)NBS * DD];
static __device__ float g_goal[(size_t)NBS * DD];
static __device__ float g_gp[(size_t)NBS * DD];
static __device__ float g_Sb[2][PLANE];          // fallback only
static __device__ float g_Yb[2][PLANE];
static __device__ float g_logits[(size_t)NBEAM * NBS * 8];
static __device__ float g_prob[2][NBEAM * NBS];
static __device__ int   g_root[2][NBEAM * NBS];
static __device__ int   g_selp[NBEAM * NBS];
static __device__ int   g_sela[NBEAM * NBS];
static __device__ float g_s1[DD], g_t1[DD], g_A1[8 * DD];
static __device__ float g_W2t[8 * DD];
static __device__ float g_mu[NBEAM * NBS], g_iv[NBEAM * NBS];
static __device__ double g_sm[2][NBEAM * NBS], g_su[2][NBEAM * NBS], g_sr[2][NBEAM * NBS];
static __device__ double g_sq[2][(size_t)NBEAM * NBS * 8];
static __device__ double g_sumA[8], g_nA[8], g_lA[8], g_AB[64], g_sumL, g_nL;
static __device__ int   g_flag;

// ---------------- helpers ----------------------------------------------------
__device__ __forceinline__ float block_sum256(float v, float* red) {
#pragma unroll
    for (int o = 16; o; o >>= 1) v += __shfl_xor_sync(0xffffffffu, v, o);
    if ((threadIdx.x & 31) == 0) red[threadIdx.x >> 5] = v;
    __syncthreads();
    float s = red[0] + red[1] + red[2] + red[3] + red[4] + red[5] + red[6] + red[7];
    __syncthreads();
    return s;
}
__device__ __forceinline__ float block_sum128(float v, float* red) {
#pragma unroll
    for (int o = 16; o; o >>= 1) v += __shfl_xor_sync(0xffffffffu, v, o);
    if ((threadIdx.x & 31) == 0) red[threadIdx.x >> 5] = v;
    __syncthreads();
    float s = red[0] + red[1] + red[2] + red[3];
    __syncthreads();
    return s;
}

__global__ void flag_k(const float* __restrict__ g) {
    __shared__ int ok;
    if (threadIdx.x == 0) ok = 1;
    __syncthreads();
    if (g[threadIdx.x] != 1.0f) atomicExch(&ok, 0);
    __syncthreads();
    if (threadIdx.x == 0) g_flag = ok;
}

// s1 = colsum(W1a); t1 = ln_b @ W1a; A1[a] = action[a] @ W1a
__global__ __launch_bounds__(128) void precomp_k(
    const float* __restrict__ W1a, const float* __restrict__ action,
    const float* __restrict__ lnb)
{
    int n = blockIdx.x, t = threadIdx.x;
    float v[10];
#pragma unroll
    for (int i = 0; i < 10; i++) v[i] = 0.f;
    for (int d = t; d < DD; d += 128) {
        float w = W1a[(size_t)d * DD + n];
        v[0] += w;
        v[1] += lnb[d] * w;
#pragma unroll
        for (int a = 0; a < 8; a++) v[2 + a] += action[a * DD + d] * w;
    }
    __shared__ float red[10][4];
    int wd = t >> 5, ln = t & 31;
#pragma unroll
    for (int i = 0; i < 10; i++) {
        float x = v[i];
#pragma unroll
        for (int o = 16; o; o >>= 1) x += __shfl_xor_sync(0xffffffffu, x, o);
        if (ln == 0) red[i][wd] = x;
    }
    __syncthreads();
    if (t < 10) {
        float s = red[t][0] + red[t][1] + red[t][2] + red[t][3];
        if (t == 0)      g_s1[n] = s;
        else if (t == 1) g_t1[n] = s;
        else             g_A1[(t - 2) * DD + n] = s;
    }
}

// double-precision action/lnb constants + W2 transpose
__global__ __launch_bounds__(256) void const_k(
    const float* __restrict__ action, const float* __restrict__ lnb,
    const float* __restrict__ W2)
{
    int a = blockIdx.x, t = threadIdx.x;
    double v[13];
#pragma unroll
    for (int i = 0; i < 13; i++) v[i] = 0.0;
    for (int d = t; d < DD; d += 256) {
        double ad = (double)action[a * DD + d];
        double ld = (double)lnb[d];
        v[0] += ad; v[1] += ad * ad; v[2] += ad * ld;
#pragma unroll
        for (int b = 0; b < 8; b++) v[3 + b] += ad * (double)action[b * DD + d];
        v[11] += ld; v[12] += ld * ld;
    }
    __shared__ double dred[13][8];
    int wp = t >> 5, ln = t & 31;
#pragma unroll
    for (int i = 0; i < 13; i++) {
        double x = v[i];
#pragma unroll
        for (int o = 16; o; o >>= 1) x += __shfl_xor_sync(0xffffffffu, x, o);
        if (ln == 0) dred[i][wp] = x;
    }
    __syncthreads();
    if (t < 13) {
        double s = 0.0;
#pragma unroll
        for (int w = 0; w < 8; w++) s += dred[t][w];
        if (t == 0)      g_sumA[a] = s;
        else if (t == 1) g_nA[a] = s;
        else if (t == 2) g_lA[a] = s;
        else if (t < 11) g_AB[a * 8 + (t - 3)] = s;
        else if (a == 0 && t == 11) g_sumL = s;
        else if (a == 0 && t == 12) g_nL = s;
    }
    if (a == 0)
        for (int idx = t; idx < 4096; idx += 256)
            g_W2t[(idx & 7) * DD + (idx >> 3)] = W2[idx];
}

// initial scalar stats of states0 (plane 0, parity 0)
__global__ __launch_bounds__(128) void initstats_k(
    const float* __restrict__ lnb, const float* __restrict__ action)
{
    int bs = blockIdx.x, t = threadIdx.x;
    float4 s = ((const float4*)(g_states0 + (size_t)bs * DD))[t];
    double a0 = s.x, a1 = s.y, a2 = s.z, a3 = s.w;
    double v[11];
    v[0] = a0 + a1 + a2 + a3;
    v[1] = a0 * a0 + a1 * a1 + a2 * a2 + a3 * a3;
    float4 l = ((const float4*)lnb)[t];
    v[2] = a0 * l.x + a1 * l.y + a2 * l.z + a3 * l.w;
#pragma unroll
    for (int b = 0; b < 8; b++) {
        float4 w = ((const float4*)(action + b * DD))[t];
        v[3 + b] = a0 * w.x + a1 * w.y + a2 * w.z + a3 * w.w;
    }
    __shared__ double dred[11][4];
    int wp = t >> 5, ln = t & 31;
#pragma unroll
    for (int i = 0; i < 11; i++) {
        double x = v[i];
#pragma unroll
        for (int o = 16; o; o >>= 1) x += __shfl_xor_sync(0xffffffffu, x, o);
        if (ln == 0) dred[i][wp] = x;
    }
    __syncthreads();
    if (t < 11) {
        double s2 = dred[t][0] + dred[t][1] + dred[t][2] + dred[t][3];
        if (t == 0)      g_sm[0][bs] = s2;
        else if (t == 1) g_su[0][bs] = s2;
        else if (t == 2) g_sr[0][bs] = s2;
        else             g_sq[0][(size_t)bs * 8 + (t - 3)] = s2;
    }
}

// frag load: 8 consecutive floats from a padded smem row
#define LDFRAG(dst, rowptr, off) do { \
    *(float4*)(dst)       = *(const float4*)&(rowptr)[(off)]; \
    *(float4*)((dst) + 4) = *(const float4*)&(rowptr)[(off) + 4]; } while (0)

// ------- batched pair of M x 512 x 512 SGEMMs (z selects problem) ------------
__global__ __launch_bounds__(256) void gemm512x2_k(
    const float* A0, const float* W0, const float* b0, float* C0, int relu0,
    const float* A1, const float* W1, const float* b1, float* C1, int relu1)
{
    const float* A = blockIdx.z ? A1 : A0;
    const float* W = blockIdx.z ? W1 : W0;
    const float* bias = blockIdx.z ? b1 : b0;
    float* C = blockIdx.z ? C1 : C0;
    int relu = blockIdx.z ? relu1 : relu0;

    __shared__ float As[2][16][132];
    __shared__ float Ws[2][16][132];
    int n0 = blockIdx.x * 128, m0 = blockIdx.y * 128;
    int tid = threadIdx.x, tm = tid >> 4, tn = tid & 15;
    float acc[8][8];
#pragma unroll
    for (int i = 0; i < 8; i++)
#pragma unroll
        for (int j = 0; j < 8; j++) acc[i][j] = 0.f;

    int r0 = tid >> 2, c0 = (tid & 3) << 2;
    int r1 = (tid + 256) >> 2, c1 = ((tid + 256) & 3) << 2;
    int rw0 = tid >> 5, cw0 = (tid & 31) << 2;
    int rw1 = (tid + 256) >> 5, cw1 = ((tid + 256) & 31) << 2;

    float4 pa0, pa1, pw0, pw1;
    pa0 = *(const float4*)(A + (size_t)(m0 + r0) * DD + c0);
    pa1 = *(const float4*)(A + (size_t)(m0 + r1) * DD + c1);
    pw0 = *(const float4*)(W + (size_t)rw0 * DD + n0 + cw0);
    pw1 = *(const float4*)(W + (size_t)rw1 * DD + n0 + cw1);
    As[0][c0][r0] = pa0.x; As[0][c0 + 1][r0] = pa0.y; As[0][c0 + 2][r0] = pa0.z; As[0][c0 + 3][r0] = pa0.w;
    As[0][c1][r1] = pa1.x; As[0][c1 + 1][r1] = pa1.y; As[0][c1 + 2][r1] = pa1.z; As[0][c1 + 3][r1] = pa1.w;
    *(float4*)&Ws[0][rw0][cw0] = pw0;
    *(float4*)&Ws[0][rw1][cw1] = pw1;
    __syncthreads();

    int buf = 0;
    for (int k0 = 0; k0 < DD; k0 += 16) {
        int nk = k0 + 16;
        if (nk < DD) {
            pa0 = *(const float4*)(A + (size_t)(m0 + r0) * DD + nk + c0);
            pa1 = *(const float4*)(A + (size_t)(m0 + r1) * DD + nk + c1);
            pw0 = *(const float4*)(W + (size_t)(nk + rw0) * DD + n0 + cw0);
            pw1 = *(const float4*)(W + (size_t)(nk + rw1) * DD + n0 + cw1);
        }
        // register-fragment double-buffered FMA loop (same FMA order as before)
        float af[2][8], bf[2][8];
        LDFRAG(af[0], As[buf][0], tm * 8);
        LDFRAG(bf[0], Ws[buf][0], tn * 8);
#pragma unroll
        for (int kk = 0; kk < 16; kk++) {
            int cu = kk & 1;
            if (kk < 15) {
                LDFRAG(af[cu ^ 1], As[buf][kk + 1], tm * 8);
                LDFRAG(bf[cu ^ 1], Ws[buf][kk + 1], tn * 8);
            }
#pragma unroll
            for (int i = 0; i < 8; i++)
#pragma unroll
                for (int j = 0; j < 8; j++) acc[i][j] += af[cu][i] * bf[cu][j];
        }
        if (nk < DD) {
            int nb = buf ^ 1;
            As[nb][c0][r0] = pa0.x; As[nb][c0 + 1][r0] = pa0.y; As[nb][c0 + 2][r0] = pa0.z; As[nb][c0 + 3][r0] = pa0.w;
            As[nb][c1][r1] = pa1.x; As[nb][c1 + 1][r1] = pa1.y; As[nb][c1 + 2][r1] = pa1.z; As[nb][c1 + 3][r1] = pa1.w;
            *(float4*)&Ws[nb][rw0][cw0] = pw0;
            *(float4*)&Ws[nb][rw1][cw1] = pw1;
            __syncthreads();
            buf = nb;
        }
    }
#pragma unroll
    for (int i = 0; i < 8; i++) {
        int row = m0 + tm * 8 + i;
#pragma unroll
        for (int j = 0; j < 8; j++) {
            int col = n0 + tn * 8 + j;
            float v = acc[i][j];
            if (bias) v += bias[col];
            if (relu) v = fmaxf(v, 0.f);
            C[(size_t)row * DD + col] = v;
        }
    }
}

// ---------------- double-buffered 128x128 triangular GEMM --------------------
__global__ __launch_bounds__(256) void gemmtri_k(
    const float* __restrict__ A, const float* __restrict__ Wt)
{
    __shared__ float As[2][16][132];
    __shared__ float Ws[2][16][132];
    int n0 = blockIdx.x * 128, m0 = blockIdx.y * 128;
    int tid = threadIdx.x, tm = tid >> 4, tn = tid & 15;
    float acc[8][8];
#pragma unroll
    for (int i = 0; i < 8; i++)
#pragma unroll
        for (int j = 0; j < 8; j++) acc[i][j] = 0.f;

    int r0 = tid >> 2, c0 = (tid & 3) << 2;
    int r1 = (tid + 256) >> 2, c1 = ((tid + 256) & 3) << 2;
    int rw0 = tid >> 5, cw0 = (tid & 31) << 2;
    int rw1 = (tid + 256) >> 5, cw1 = ((tid + 256) & 31) << 2;

    auto loadw = [&](int k0, int r, int c) -> float4 {
        int tt = k0 + r;
        if (k0 - n0 < 128) {
            int s = n0 + c;
            float4 w;
            w.x = (tt >= s    ) ? Wt[(size_t)tt * WLD + s    ] : 0.f;
            w.y = (tt >= s + 1) ? Wt[(size_t)tt * WLD + s + 1] : 0.f;
            w.z = (tt >= s + 2) ? Wt[(size_t)tt * WLD + s + 2] : 0.f;
            w.w = (tt >= s + 3) ? Wt[(size_t)tt * WLD + s + 3] : 0.f;
            return w;
        }
        return *(const float4*)(Wt + (size_t)tt * WLD + n0 + c);
    };

    float4 pa0, pa1, pw0, pw1;
    pa0 = *(const float4*)(A + (size_t)(m0 + r0) * SS + n0 + c0);
    pa1 = *(const float4*)(A + (size_t)(m0 + r1) * SS + n0 + c1);
    pw0 = loadw(n0, rw0, cw0);
    pw1 = loadw(n0, rw1, cw1);
    As[0][c0][r0] = pa0.x; As[0][c0 + 1][r0] = pa0.y; As[0][c0 + 2][r0] = pa0.z; As[0][c0 + 3][r0] = pa0.w;
    As[0][c1][r1] = pa1.x; As[0][c1 + 1][r1] = pa1.y; As[0][c1 + 2][r1] = pa1.z; As[0][c1 + 3][r1] = pa1.w;
    *(float4*)&Ws[0][rw0][cw0] = pw0;
    *(float4*)&Ws[0][rw1][cw1] = pw1;
    __syncthreads();

    int buf = 0;
    for (int k0 = n0; k0 < SS; k0 += 16) {
        int nk = k0 + 16;
        if (nk < SS) {
            pa0 = *(const float4*)(A + (size_t)(m0 + r0) * SS + nk + c0);
            pa1 = *(const float4*)(A + (size_t)(m0 + r1) * SS + nk + c1);
            pw0 = loadw(nk, rw0, cw0);
            pw1 = loadw(nk, rw1, cw1);
        }
        float af[2][8], bf[2][8];
        LDFRAG(af[0], As[buf][0], tm * 8);
        LDFRAG(bf[0], Ws[buf][0], tn * 8);
#pragma unroll
        for (int kk = 0; kk < 16; kk++) {
            int cu = kk & 1;
            if (kk < 15) {
                LDFRAG(af[cu ^ 1], As[buf][kk + 1], tm * 8);
                LDFRAG(bf[cu ^ 1], Ws[buf][kk + 1], tn * 8);
            }
#pragma unroll
            for (int i = 0; i < 8; i++)
#pragma unroll
                for (int j = 0; j < 8; j++) acc[i][j] += af[cu][i] * bf[cu][j];
        }
        if (nk < SS) {
            int nb = buf ^ 1;
            As[nb][c0][r0] = pa0.x; As[nb][c0 + 1][r0] = pa0.y; As[nb][c0 + 2][r0] = pa0.z; As[nb][c0 + 3][r0] = pa0.w;
            As[nb][c1][r1] = pa1.x; As[nb][c1 + 1][r1] = pa1.y; As[nb][c1 + 2][r1] = pa1.z; As[nb][c1 + 3][r1] = pa1.w;
            *(float4*)&Ws[nb][rw0][cw0] = pw0;
            *(float4*)&Ws[nb][rw1][cw1] = pw1;
            __syncthreads();
            buf = nb;
        }
    }
#pragma unroll
    for (int i = 0; i < 8; i++) {
        int row = m0 + tm * 8 + i;
#pragma unroll
        for (int j = 0; j < 8; j++)
            g_c[(size_t)row * SS + n0 + tn * 8 + j] = fmaxf(acc[i][j], 0.f);
    }
}

// ---------------- transposes -------------------------------------------------
__global__ void transpose_c_k() {
    __shared__ float tile[32][33];
    int b = blockIdx.z, s0 = blockIdx.x * 32, d0 = blockIdx.y * 32;
    int tx = threadIdx.x, ty = threadIdx.y;
#pragma unroll
    for (int i = 0; i < 32; i += 8)
        tile[ty + i][tx] = g_c[(size_t)(b * DD + d0 + ty + i) * SS + s0 + tx];
    __syncthreads();
#pragma unroll
    for (int i = 0; i < 32; i += 8)
        g_ct[(size_t)(b * SS + s0 + ty + i) * DD + d0 + tx] = tile[tx][ty + i];
}
__global__ void transpose_out_k(float* __restrict__ out) {
    __shared__ float tile[32][33];
    int b = blockIdx.z, d0 = blockIdx.x * 32, s0 = blockIdx.y * 32;
    int tx = threadIdx.x, ty = threadIdx.y;
#pragma unroll
    for (int i = 0; i < 32; i += 8)
        tile[ty + i][tx] = g_h[(size_t)(b * SS + s0 + ty + i) * DD + d0 + tx];
    __syncthreads();
#pragma unroll
    for (int i = 0; i < 32; i += 8)
        out[(size_t)(b * DD + d0 + ty + i) * SS + s0 + tx] = tile[tx][ty + i];
}

// ---------------- misc init --------------------------------------------------
__global__ void copy_k() {
    size_t i = (size_t)blockIdx.x * 256 + threadIdx.x;
    ((float4*)g_Sb[0])[i] = ((const float4*)g_states0)[i];
}
__global__ void initprob_k() {
    int bs = blockIdx.x * 256 + threadIdx.x;
    if (bs < NBS) g_prob[0][bs] = 1.0f;
}

// ---------------- turn-0 logits: relu(Y0 + gp) @ W2 + b2 ---------------------
__global__ __launch_bounds__(256) void logits0_k(
    const float* __restrict__ W2, const float* __restrict__ b2)
{
    __shared__ float sW[512][9];
    __shared__ float sb[8];
    int tid = threadIdx.x;
    for (int idx = tid; idx < 4096; idx += 256) sW[idx >> 3][idx & 7] = W2[idx];
    if (tid < 8) sb[tid] = b2[tid];
    __syncthreads();
    int row = blockIdx.x * 8 + (tid >> 5);
    int lane = tid & 31;
    const float* Y  = g_Yb[0] + (size_t)row * DD;
    const float* gp = g_gp + (size_t)row * DD;
    float acc[8] = {0, 0, 0, 0, 0, 0, 0, 0};
#pragma unroll
    for (int j = 0; j < 16; j++) {
        int n = lane + j * 32;
        float h = fmaxf(Y[n] + gp[n], 0.f);
#pragma unroll
        for (int a = 0; a < 8; a++) acc[a] += h * sW[n][a];
    }
#pragma unroll
    for (int a = 0; a < 8; a++) {
        float v = acc[a];
#pragma unroll
        for (int o = 16; o; o >>= 1) v += __shfl_xor_sync(0xffffffffu, v, o);
        if (lane == 0) g_logits[(size_t)row * 8 + a] = v + sb[a];
    }
}

// -------- warp-per-bs: softmax + top-k + scalar-stat recursion ---------------
__global__ __launch_bounds__(256) void select_k(int cur, int beam_now, int beam_next, int turn) {
    int warp = threadIdx.x >> 5, lane = threadIdx.x & 31;
    int bs = blockIdx.x * 8 + warp;
    int nxt = cur ^ 1;
    float c[8];
    if (lane < beam_now) {
        const float* lp = g_logits + ((size_t)lane * NBS + bs) * 8;
        float l[8], m = -1e30f;
#pragma unroll
        for (int a = 0; a < 8; a++) { l[a] = lp[a]; m = fmaxf(m, l[a]); }
        float s = 0.f;
#pragma unroll
        for (int a = 0; a < 8; a++) { l[a] = expf(l[a] - m); s += l[a]; }
        float pk = g_prob[cur][lane * NBS + bs];
#pragma unroll
        for (int a = 0; a < 8; a++) c[a] = pk * (l[a] / s);
    } else {
#pragma unroll
        for (int a = 0; a < 8; a++) c[a] = -2.f;
    }
    float myv = 0.f; int myi = 0;
    for (int k = 0; k < beam_next; k++) {
        float v = -3.f; int id = 0x7fffffff;
#pragma unroll
        for (int a = 0; a < 8; a++)
            if (c[a] > v) { v = c[a]; id = lane * 8 + a; }
#pragma unroll
        for (int o = 16; o; o >>= 1) {
            float ov = __shfl_xor_sync(0xffffffffu, v, o);
            int   oi = __shfl_xor_sync(0xffffffffu, id, o);
            if (ov > v || (ov == v && oi < id)) { v = ov; id = oi; }
        }
        if ((id >> 3) == lane) c[id & 7] = -1.f;
        if (lane == k) { myv = v; myi = id; }
    }
    if (lane < beam_next) {
        int parent = myi >> 3, act = myi & 7;
        int ci = lane * NBS + bs;
        g_prob[nxt][ci] = myv;
        g_selp[ci] = parent;
        g_sela[ci] = act;
        g_root[nxt][ci] = (turn == 0) ? act : g_root[cur][parent * NBS + bs];
        size_t pi = (size_t)parent * NBS + bs;
        double m  = g_sm[cur][pi], u = g_su[cur][pi], r = g_sr[cur][pi];
        const double* qp = &g_sq[cur][pi * 8];
        double sum_h = m + g_sumA[act];
        double mu = sum_h * (1.0 / 512.0);
        double hh = u + 2.0 * qp[act] + g_nA[act];
        double var = hh * (1.0 / 512.0) - mu * mu;
        double inv = rsqrt(var + 1e-5);
        g_mu[ci] = (float)mu;
        g_iv[ci] = (float)inv;
        double hml = r + g_lA[act] - mu * g_sumL;
        size_t ciw = (size_t)lane * NBS + bs;
        g_sm[nxt][ciw] = inv * (sum_h - 512.0 * mu) + g_sumL;
        g_su[nxt][ciw] = inv * inv * (hh - 512.0 * mu * mu) + 2.0 * inv * hml + g_nL;
        g_sr[nxt][ciw] = inv * hml + g_nL;
        double* qn = &g_sq[nxt][ciw * 8];
#pragma unroll
        for (int b = 0; b < 8; b++)
            qn[b] = inv * (qp[b] + g_AB[act * 8 + b] - mu * g_sumA[b]) + g_lA[b];
    }
}

// ---------------- fused update: Y recursion + logits --------------------------
__global__ __launch_bounds__(128) void update_k(
    int cur, const float* __restrict__ action, const float* __restrict__ lng,
    const float* __restrict__ lnb, const float* __restrict__ W1a,
    const float* __restrict__ b2, int store)
{
    __shared__ float sred[4][8];
    int bs = blockIdx.x, k = blockIdx.y, nxt = cur ^ 1, t = threadIdx.x;
    int ki = k * NBS + bs;
    int p = g_selp[ki], a = g_sela[ki];
    const float* Yp = g_Yb[cur] + ((size_t)p * NBS + bs) * DD;
    float* Yn       = g_Yb[nxt] + ((size_t)k * NBS + bs) * DD;
    const float4* gp4 = (const float4*)(g_gp + (size_t)bs * DD);
    float acc[8] = {0, 0, 0, 0, 0, 0, 0, 0};

    if (g_flag) {
        float mu = g_mu[ki], inv = g_iv[ki];
        float4 yp = ((const float4*)Yp)[t];
        float4 aa = ((const float4*)(g_A1 + a * DD))[t];
        float4 ss = ((const float4*)g_s1)[t];
        float4 tt = ((const float4*)g_t1)[t];
        float4 gg = gp4[t];
        float4 y;
        y.x = fmaf(inv, yp.x + aa.x - mu * ss.x, tt.x);
        y.y = fmaf(inv, yp.y + aa.y - mu * ss.y, tt.y);
        y.z = fmaf(inv, yp.z + aa.z - mu * ss.z, tt.z);
        y.w = fmaf(inv, yp.w + aa.w - mu * ss.w, tt.w);
        if (store) ((float4*)Yn)[t] = y;
        float h0 = fmaxf(y.x + gg.x, 0.f), h1 = fmaxf(y.y + gg.y, 0.f);
        float h2 = fmaxf(y.z + gg.z, 0.f), h3 = fmaxf(y.w + gg.w, 0.f);
#pragma unroll
        for (int b = 0; b < 8; b++) {
            float4 w = ((const float4*)(g_W2t + b * DD))[t];
            acc[b] = fmaf(h0, w.x, fmaf(h1, w.y, fmaf(h2, w.z, fmaf(h3, w.w, acc[b]))));
        }
    } else {
        __shared__ float sn[512];
        __shared__ float red[4];
        const float* Sp = g_Sb[cur] + ((size_t)p * NBS + bs) * DD;
        float* Sn       = g_Sb[nxt] + ((size_t)k * NBS + bs) * DD;
        float4 sp = ((const float4*)Sp)[t];
        float4 av = ((const float4*)(action + a * DD))[t];
        float h[4] = {sp.x + av.x, sp.y + av.y, sp.z + av.z, sp.w + av.w};
        float mu = block_sum128(h[0] + h[1] + h[2] + h[3], red) * (1.f / 512.f);
        float d0 = h[0] - mu, d1 = h[1] - mu, d2 = h[2] - mu, d3 = h[3] - mu;
        float var = block_sum128(d0 * d0 + d1 * d1 + d2 * d2 + d3 * d3, red) * (1.f / 512.f);
        float inv = rsqrtf(var + 1e-5f);
        float4 gv = ((const float4*)lng)[t];
        float4 bvv = ((const float4*)lnb)[t];
        float v0 = d0 * inv * gv.x + bvv.x, v1 = d1 * inv * gv.y + bvv.y;
        float v2 = d2 * inv * gv.z + bvv.z, v3 = d3 * inv * gv.w + bvv.w;
        sn[4 * t] = v0; sn[4 * t + 1] = v1; sn[4 * t + 2] = v2; sn[4 * t + 3] = v3;
        if (store) { float4 o = {v0, v1, v2, v3}; ((float4*)Sn)[t] = o; }
        __syncthreads();
        float ya[4];
#pragma unroll
        for (int j = 0; j < 4; j++) {
            int n = 4 * t + j;
            float ac = 0.f;
            for (int d = 0; d < DD; d++) ac += sn[d] * W1a[(size_t)d * DD + n];
            ya[j] = ac;
            if (store) Yn[n] = ac;
        }
        float4 gg = gp4[t];
        float h0 = fmaxf(ya[0] + gg.x, 0.f), h1 = fmaxf(ya[1] + gg.y, 0.f);
        float h2 = fmaxf(ya[2] + gg.z, 0.f), h3 = fmaxf(ya[3] + gg.w, 0.f);
#pragma unroll
        for (int b = 0; b < 8; b++) {
            float4 w = ((const float4*)(g_W2t + b * DD))[t];
            acc[b] = fmaf(h0, w.x, fmaf(h1, w.y, fmaf(h2, w.z, fmaf(h3, w.w, acc[b]))));
        }
    }
    int lane = t & 31, wp = t >> 5;
#pragma unroll
    for (int b = 0; b < 8; b++) {
        float v = acc[b];
#pragma unroll
        for (int o = 16; o; o >>= 1) v += __shfl_xor_sync(0xffffffffu, v, o);
        if (lane == 0) sred[wp][b] = v;
    }
    __syncthreads();
    if (t < 8)
        g_logits[(size_t)ki * 8 + t] = sred[0][t] + sred[1][t] + sred[2][t] + sred[3][t] + b2[t];
}

// ---------------- final: LN(states0 + action[root0]) -------------------------
__global__ __launch_bounds__(256) void final_k(
    int par, const float* __restrict__ action, const float* __restrict__ lng,
    const float* __restrict__ lnb)
{
    __shared__ float red[8];
    int bs = blockIdx.x, t = threadIdx.x;
    int r = g_root[par][bs];
    float h0 = g_states0[(size_t)bs * DD + t]       + action[r * DD + t];
    float h1 = g_states0[(size_t)bs * DD + t + 256] + action[r * DD + t + 256];
    float mu = block_sum256(h0 + h1, red) * (1.f / 512.f);
    float d0 = h0 - mu, d1 = h1 - mu;
    float var = block_sum256(d0 * d0 + d1 * d1, red) * (1.f / 512.f);
    float inv = rsqrtf(var + 1e-5f);
    g_h[(size_t)bs * DD + t]       = d0 * inv * lng[t]       + lnb[t];
    g_h[(size_t)bs * DD + t + 256] = d1 * inv * lng[t + 256] + lnb[t + 256];
}

// ---------------- launch ------------------------------------------------------
extern "C" void kernel_launch(void* const* d_in, const int* in_sizes, int n_in,
                              void* d_out, int out_size)
{
    const float* x      = (const float*)d_in[0];
    const float* weight = (const float*)d_in[1];
    const float* c2s_w1 = (const float*)d_in[2];
    const float* c2s_b1 = (const float*)d_in[3];
    const float* c2s_w2 = (const float*)d_in[4];
    const float* c2s_b2 = (const float*)d_in[5];
    const float* eg_w1  = (const float*)d_in[6];
    const float* eg_b1  = (const float*)d_in[7];
    const float* eg_w2  = (const float*)d_in[8];
    const float* eg_b2  = (const float*)d_in[9];
    const float* gna_w1 = (const float*)d_in[10];
    const float* gna_b1 = (const float*)d_in[11];
    const float* gna_w2 = (const float*)d_in[12];
    const float* gna_b2 = (const float*)d_in[13];
    const float* action = (const float*)d_in[14];
    const float* ln_g   = (const float*)d_in[15];
    const float* ln_b   = (const float*)d_in[16];

    float *p_ct, *p_h, *p_h2, *p_s0, *p_goal, *p_gp, *p_Y;
    cudaGetSymbolAddress((void**)&p_ct,   g_ct);
    cudaGetSymbolAddress((void**)&p_h,    g_h);
    cudaGetSymbolAddress((void**)&p_h2,   g_h2);
    cudaGetSymbolAddress((void**)&p_s0,   g_states0);
    cudaGetSymbolAddress((void**)&p_goal, g_goal);
    cudaGetSymbolAddress((void**)&p_gp,   g_gp);
    cudaGetSymbolAddress((void**)&p_Y,    g_Yb);
    const float* W1a = gna_w1;
    const float* W1b = gna_w1 + DD * DD;

    flag_k<<<1, 512>>>(ln_g);
    precomp_k<<<512, 128>>>(W1a, action, ln_b);
    const_k<<<8, 256>>>(action, ln_b, gna_w2);
    gemmtri_k<<<dim3(16, 16), 256>>>(x, weight);
    transpose_c_k<<<dim3(64, 16, 4), dim3(32, 8)>>>();
    gemm512x2_k<<<dim3(4, 64, 2), 256>>>(p_ct, c2s_w1, c2s_b1, p_h,  1,
                                         p_ct, eg_w1,  eg_b1,  p_h2, 1);
    gemm512x2_k<<<dim3(4, 64, 2), 256>>>(p_h,  c2s_w2, c2s_b2, p_s0,   0,
                                         p_h2, eg_w2,  eg_b2,  p_goal, 0);
    gemm512x2_k<<<dim3(4, 64, 2), 256>>>(p_goal, W1b, gna_b1, p_gp, 0,
                                         p_s0,   W1a, nullptr, p_Y, 0);
    copy_k<<<4096, 256>>>();
    initprob_k<<<32, 256>>>();
    initstats_k<<<8192, 128>>>(ln_b, action);
    logits0_k<<<1024, 256>>>(gna_w2, gna_b2);

    int cur = 0;
    const int bn[7] = {1, 8, 10, 10, 10, 10, 10};
    const int bx[7] = {8, 10, 10, 10, 10, 10, 10};
    for (int t = 0; t < 7; t++) {
        select_k<<<1024, 256>>>(cur, bn[t], bx[t], t);
        if (t < 6)
            update_k<<<dim3(NBS, bx[t]), 128>>>(cur, action, ln_g, ln_b, W1a,
                                                gna_b2, (t < 5) ? 1 : 0);
        cur ^= 1;
    }
    final_k<<<8192, 256>>>(cur, action, ln_g, ln_b);
    transpose_out_k<<<dim3(16, 64, 4), dim3(32, 8)>>>((float*)d_out);
}